// round 8
// baseline (speedup 1.0000x reference)
#include <cuda_runtime.h>
#include <cstdint>

#define B_ 4
#define L_ 2048
#define D_ 512
#define H_ 8
#define E_ 64

// Projected Q/K/V scratch, [B,H,L,E] (each (b,h) slice is contiguous [L,E]).
__device__ __align__(256) float g_q[B_ * H_ * L_ * E_];
__device__ __align__(256) float g_k[B_ * H_ * L_ * E_];
__device__ __align__(256) float g_v[B_ * H_ * L_ * E_];

// ---------------------------------------------------------------------------
// helpers
// ---------------------------------------------------------------------------
__device__ __forceinline__ uint32_t smem_u32(const void* p) {
    uint32_t a;
    asm("{ .reg .u64 t; cvta.to.shared.u64 t, %1; cvt.u32.u64 %0, t; }"
        : "=r"(a) : "l"(p));
    return a;
}

// Round fp32 -> nearest tf32 (kills the truncation bias of the MMA datapath).
__device__ __forceinline__ uint32_t rna(float x) {
    uint32_t r;
    asm("cvt.rna.tf32.f32 %0, %1;" : "=r"(r) : "f"(x));
    return r;
}

// D = A(16x8,row) * B(8x8,col) + D, tf32 inputs
__device__ __forceinline__ void mma_tf32(float* d, const uint32_t* a, const uint32_t* b) {
    asm volatile(
        "mma.sync.aligned.m16n8k8.row.col.f32.tf32.tf32.f32 "
        "{%0,%1,%2,%3}, {%4,%5,%6,%7}, {%8,%9}, {%0,%1,%2,%3};"
        : "+f"(d[0]), "+f"(d[1]), "+f"(d[2]), "+f"(d[3])
        : "r"(a[0]), "r"(a[1]), "r"(a[2]), "r"(a[3]), "r"(b[0]), "r"(b[1]));
}

__device__ __forceinline__ void cp16(uint32_t dst, const void* src) {
    asm volatile("cp.async.cg.shared.global [%0], [%1], 16;"
                 :: "r"(dst), "l"(src) : "memory");
}
#define CP_COMMIT() asm volatile("cp.async.commit_group;" ::: "memory")
#define CP_WAIT(n)  asm volatile("cp.async.wait_group %0;" :: "n"(n) : "memory")

// ---------------------------------------------------------------------------
// Kernel 1: QKV projection (1x tf32, RN-rounded operands).
// CTA 128x128, 8 warps (2M x 4N), K=512 in BK=32 chunks, double buffer.
// grid (64, 4, 3), 256 thr.
// ---------------------------------------------------------------------------
static constexpr int PJ_XS = 128 * 36;
static constexpr int PJ_WS = 32 * 136;
static constexpr int PJ_SMEM = (2 * PJ_XS + 2 * PJ_WS) * 4;   // 71680 B

__global__ void __launch_bounds__(256) proj_mma(
    const float* __restrict__ X0, const float* __restrict__ X1,
    const float* __restrict__ X2,
    const float* __restrict__ W0, const float* __restrict__ W1,
    const float* __restrict__ W2,
    const float* __restrict__ b0, const float* __restrict__ b1,
    const float* __restrict__ b2)
{
    extern __shared__ float smf[];
    float* Xs = smf;
    float* Ws = smf + 2 * PJ_XS;
    uint32_t sX = smem_u32(Xs), sW = smem_u32(Ws);

    int z = blockIdx.z;
    const float* X = (z == 0) ? X0 : (z == 1) ? X1 : X2;
    const float* W = (z == 0) ? W0 : (z == 1) ? W1 : W2;
    const float* bias = (z == 0) ? b0 : (z == 1) ? b1 : b2;
    float* dst = (z == 0) ? g_q : (z == 1) ? g_k : g_v;

    int t = threadIdx.x;
    int lane = t & 31, wid = t >> 5;
    int gid = lane >> 2, tg = lane & 3;
    int warpM = wid >> 2, warpN = wid & 3;
    int m0 = blockIdx.x * 128, n0 = blockIdx.y * 128;

    float acc[4][4][4] = {};

    auto stage = [&](int kt, int buf) {
        int k0 = kt * 32;
#pragma unroll
        for (int i = 0; i < 4; i++) {
            int idx = t + i * 256;
            int row = idx >> 3, cc = (idx & 7) * 4;
            cp16(sX + (buf * PJ_XS + row * 36 + cc) * 4,
                 X + (size_t)(m0 + row) * D_ + k0 + cc);
        }
#pragma unroll
        for (int i = 0; i < 4; i++) {
            int idx = t + i * 256;
            int row = idx >> 5, cc = (idx & 31) * 4;
            cp16(sW + (buf * PJ_WS + row * 136 + cc) * 4,
                 W + (size_t)(k0 + row) * D_ + n0 + cc);
        }
    };

    stage(0, 0); CP_COMMIT();
    const int NIT = D_ / 32;                 // 16
    for (int kt = 0; kt < NIT; kt++) {
        int p = kt & 1;
        if (kt + 1 < NIT) { stage(kt + 1, p ^ 1); CP_COMMIT(); CP_WAIT(1); }
        else              { CP_WAIT(0); }
        __syncthreads();

        const float* Ab = Xs + p * PJ_XS;
        const float* Bb = Ws + p * PJ_WS;
#pragma unroll
        for (int ks = 0; ks < 4; ks++) {
            int k0 = ks * 8;
            uint32_t a[4][4], b[4][2];
#pragma unroll
            for (int mt = 0; mt < 4; mt++) {
                const float* pa = Ab + (warpM * 64 + mt * 16 + gid) * 36 + k0 + tg;
                a[mt][0] = rna(pa[0]);
                a[mt][1] = rna(pa[8 * 36]);
                a[mt][2] = rna(pa[4]);
                a[mt][3] = rna(pa[8 * 36 + 4]);
            }
#pragma unroll
            for (int nt = 0; nt < 4; nt++) {
                const float* pb = Bb + (k0 + tg) * 136 + warpN * 32 + nt * 8 + gid;
                b[nt][0] = rna(pb[0]);
                b[nt][1] = rna(pb[4 * 136]);
            }
#pragma unroll
            for (int mt = 0; mt < 4; mt++)
#pragma unroll
                for (int nt = 0; nt < 4; nt++)
                    mma_tf32(acc[mt][nt], a[mt], b[nt]);
        }
        __syncthreads();
    }

#pragma unroll
    for (int mt = 0; mt < 4; mt++) {
        int m = m0 + warpM * 64 + mt * 16 + gid;
        int bb = m >> 11;
        int l  = m & (L_ - 1);
#pragma unroll
        for (int nt = 0; nt < 4; nt++) {
            int n = n0 + warpN * 32 + nt * 8 + tg * 2;
            int h = n >> 6, e = n & 63;
            float2 bi = *reinterpret_cast<const float2*>(bias + n);
            *reinterpret_cast<float2*>(dst + (((size_t)(bb * H_ + h)) * L_ + l) * E_ + e) =
                make_float2(acc[mt][nt][0] + bi.x, acc[mt][nt][1] + bi.y);
            *reinterpret_cast<float2*>(dst + (((size_t)(bb * H_ + h)) * L_ + l + 8) * E_ + e) =
                make_float2(acc[mt][nt][2] + bi.x, acc[mt][nt][3] + bi.y);
        }
    }
}

// ---------------------------------------------------------------------------
// Kernel 2: FUSED scores + softmax + AV.
// Each CTA owns a 128-row stripe of one (b,h): rows m0..m0+127, all 2048 cols.
// Pass A: stream K tiles, S=exp(scale*QK^T) fragments, accumulate row sums
//         (registers only, nothing written).
// Pass B: recompute S (deterministic, bit-identical), scale by 1/rowsum,
//         write normalized attn ONCE, stage via SMEM, AV-MMA into out accum.
// grid (16, 32), 256 threads, 8 warps.
// SMEM (floats): Qs[128][68] | Ks[2][128][68] | Vs[2][128][68] | Sst[128][68]
//                | rowinv[128]   = 209408 B   (all row strides 272 B, 16-aligned)
// ---------------------------------------------------------------------------
static constexpr int F_QS  = 0;
static constexpr int F_KS  = 8704;            // 2 buffers of 128*68
static constexpr int F_VS  = F_KS + 2 * 8704; // 2 buffers of 128*68
static constexpr int F_SST = F_VS + 2 * 8704;
static constexpr int F_RI  = F_SST + 8704;
static constexpr int F_SMEM = (F_RI + 128) * 4;   // 209408 B

__global__ void __launch_bounds__(256, 1) fused_attn(float* __restrict__ attn,
                                                     float* __restrict__ out)
{
    extern __shared__ float smf[];
    float* Qs = smf + F_QS;
    float* Ks = smf + F_KS;
    float* Vs = smf + F_VS;
    float* Sst = smf + F_SST;
    float* rowinv = smf + F_RI;
    uint32_t sQ = smem_u32(Qs), sK = smem_u32(Ks), sV = smem_u32(Vs);

    int t = threadIdx.x;
    int lane = t & 31, wid = t >> 5;
    int gid = lane >> 2, tg = lane & 3;
    int warpM = wid >> 2, warpN = wid & 3;      // S-tile tiling: 2M x 4N (64x32)
    int warpM2 = wid >> 1, warpN2 = wid & 1;    // out tiling:    4M x 2N (32x32)
    int m0 = blockIdx.x * 128, bh = blockIdx.y;
    int bb = bh >> 3, h = bh & 7;

    const float* Q = g_q + (size_t)bh * L_ * E_;
    const float* K = g_k + (size_t)bh * L_ * E_;
    const float* V = g_v + (size_t)bh * L_ * E_;
    float* S = attn + (size_t)bh * L_ * L_;

    // Q stripe: resident whole kernel
#pragma unroll
    for (int i = 0; i < 8; i++) {
        int idx = t + i * 256;
        int row = idx >> 4, cc = (idx & 15) * 4;
        cp16(sQ + (row * 68 + cc) * 4, Q + (size_t)(m0 + row) * E_ + cc);
    }
    CP_COMMIT();

    auto stageK = [&](int tile, int buf) {
#pragma unroll
        for (int i = 0; i < 8; i++) {
            int idx = t + i * 256;
            int row = idx >> 4, cc = (idx & 15) * 4;
            cp16(sK + (buf * 8704 + row * 68 + cc) * 4,
                 K + (size_t)(tile * 128 + row) * E_ + cc);
        }
    };
    auto stageV = [&](int tile, int buf) {
#pragma unroll
        for (int i = 0; i < 8; i++) {
            int idx = t + i * 256;
            int row = idx >> 4, cc = (idx & 15) * 4;
            cp16(sV + (buf * 8704 + row * 68 + cc) * 4,
                 V + (size_t)(tile * 128 + row) * E_ + cc);
        }
    };

    const float scale = 0.125f;

    // ---------------- pass A: row sums only ----------------
    stageK(0, 0); CP_COMMIT();
    float rowpart[4][2] = {};
    for (int tile = 0; tile < 16; tile++) {
        int p = tile & 1;
        if (tile + 1 < 16) { stageK(tile + 1, p ^ 1); CP_COMMIT(); CP_WAIT(1); }
        else               { CP_WAIT(0); }
        __syncthreads();

        const float* Kb = Ks + p * 8704;
        float acc[4][4][4] = {};
#pragma unroll
        for (int ks = 0; ks < 8; ks++) {
            int k0 = ks * 8;
            uint32_t a[4][4], b[4][2];
#pragma unroll
            for (int mt = 0; mt < 4; mt++) {
                const float* pa = Qs + (warpM * 64 + mt * 16 + gid) * 68 + k0 + tg;
                a[mt][0] = rna(pa[0]);
                a[mt][1] = rna(pa[8 * 68]);
                a[mt][2] = rna(pa[4]);
                a[mt][3] = rna(pa[8 * 68 + 4]);
            }
#pragma unroll
            for (int nt = 0; nt < 4; nt++) {
                const float* pb = Kb + (warpN * 32 + nt * 8 + gid) * 68 + k0 + tg;
                b[nt][0] = rna(pb[0]);
                b[nt][1] = rna(pb[4]);
            }
#pragma unroll
            for (int mt = 0; mt < 4; mt++)
#pragma unroll
                for (int nt = 0; nt < 4; nt++)
                    mma_tf32(acc[mt][nt], a[mt], b[nt]);
        }
#pragma unroll
        for (int mt = 0; mt < 4; mt++)
#pragma unroll
            for (int nt = 0; nt < 4; nt++) {
                rowpart[mt][0] += __expf(acc[mt][nt][0] * scale)
                                + __expf(acc[mt][nt][1] * scale);
                rowpart[mt][1] += __expf(acc[mt][nt][2] * scale)
                                + __expf(acc[mt][nt][3] * scale);
            }
        __syncthreads();
    }

    // reduce row sums: over tg lanes, then across warpN via SMEM (reuse Sst)
#pragma unroll
    for (int mt = 0; mt < 4; mt++)
#pragma unroll
        for (int half = 0; half < 2; half++) {
            float v = rowpart[mt][half];
            v += __shfl_xor_sync(0xffffffffu, v, 1);
            v += __shfl_xor_sync(0xffffffffu, v, 2);
            if (tg == 0)
                Sst[warpN * 128 + warpM * 64 + mt * 16 + gid + half * 8] = v;
        }
    __syncthreads();
    if (t < 128)
        rowinv[t] = 1.0f / (Sst[t] + Sst[128 + t] + Sst[256 + t] + Sst[384 + t]);
    __syncthreads();

    // ---------------- pass B: recompute, normalize, write attn, AV ----------
    float oacc[2][4][4] = {};
    stageK(0, 0); CP_COMMIT();
    stageV(0, 0); CP_COMMIT();
    for (int tile = 0; tile < 16; tile++) {
        int p = tile & 1;
        if (tile + 1 < 16) {
            stageK(tile + 1, p ^ 1); CP_COMMIT();
            stageV(tile + 1, p ^ 1); CP_COMMIT();
            CP_WAIT(2);
        } else { CP_WAIT(0); }
        __syncthreads();

        const float* Kb = Ks + p * 8704;
        const float* Vb = Vs + p * 8704;

        // recompute S fragments (bit-identical to pass A)
        float acc[4][4][4] = {};
#pragma unroll
        for (int ks = 0; ks < 8; ks++) {
            int k0 = ks * 8;
            uint32_t a[4][4], b[4][2];
#pragma unroll
            for (int mt = 0; mt < 4; mt++) {
                const float* pa = Qs + (warpM * 64 + mt * 16 + gid) * 68 + k0 + tg;
                a[mt][0] = rna(pa[0]);
                a[mt][1] = rna(pa[8 * 68]);
                a[mt][2] = rna(pa[4]);
                a[mt][3] = rna(pa[8 * 68 + 4]);
            }
#pragma unroll
            for (int nt = 0; nt < 4; nt++) {
                const float* pb = Kb + (warpN * 32 + nt * 8 + gid) * 68 + k0 + tg;
                b[nt][0] = rna(pb[0]);
                b[nt][1] = rna(pb[4]);
            }
#pragma unroll
            for (int mt = 0; mt < 4; mt++)
#pragma unroll
                for (int nt = 0; nt < 4; nt++)
                    mma_tf32(acc[mt][nt], a[mt], b[nt]);
        }

        // normalize in-register + write attn (single write of normalized attn)
#pragma unroll
        for (int mt = 0; mt < 4; mt++) {
            int rl0 = warpM * 64 + mt * 16 + gid;
            float i0 = rowinv[rl0], i1 = rowinv[rl0 + 8];
#pragma unroll
            for (int nt = 0; nt < 4; nt++) {
                int cc = tile * 128 + warpN * 32 + nt * 8 + tg * 2;
                float p0 = __expf(acc[mt][nt][0] * scale) * i0;
                float p1 = __expf(acc[mt][nt][1] * scale) * i0;
                float p2 = __expf(acc[mt][nt][2] * scale) * i1;
                float p3 = __expf(acc[mt][nt][3] * scale) * i1;
                *reinterpret_cast<float2*>(S + (size_t)(m0 + rl0) * L_ + cc) =
                    make_float2(p0, p1);
                *reinterpret_cast<float2*>(S + (size_t)(m0 + rl0 + 8) * L_ + cc) =
                    make_float2(p2, p3);
                acc[mt][nt][0] = p0; acc[mt][nt][1] = p1;
                acc[mt][nt][2] = p2; acc[mt][nt][3] = p3;
            }
        }

        // AV in two 64-col halves staged through Sst
#pragma unroll
        for (int half = 0; half < 2; half++) {
            __syncthreads();
            if ((warpN >> 1) == half) {
                int cl = (warpN & 1) * 32;
#pragma unroll
                for (int mt = 0; mt < 4; mt++) {
                    int rl = warpM * 64 + mt * 16 + gid;
#pragma unroll
                    for (int nt = 0; nt < 4; nt++) {
                        int cc = cl + nt * 8 + tg * 2;
                        *reinterpret_cast<float2*>(Sst + rl * 68 + cc) =
                            make_float2(acc[mt][nt][0], acc[mt][nt][1]);
                        *reinterpret_cast<float2*>(Sst + (rl + 8) * 68 + cc) =
                            make_float2(acc[mt][nt][2], acc[mt][nt][3]);
                    }
                }
            }
            __syncthreads();

#pragma unroll
            for (int ks = 0; ks < 8; ks++) {
                int k0 = ks * 8;
                uint32_t a2[2][4], b2[4][2];
#pragma unroll
                for (int mt = 0; mt < 2; mt++) {
                    const float* pa = Sst + (warpM2 * 32 + mt * 16 + gid) * 68 + k0 + tg;
                    a2[mt][0] = rna(pa[0]);
                    a2[mt][1] = rna(pa[8 * 68]);
                    a2[mt][2] = rna(pa[4]);
                    a2[mt][3] = rna(pa[8 * 68 + 4]);
                }
#pragma unroll
                for (int nt = 0; nt < 4; nt++) {
                    const float* pb = Vb + (half * 64 + k0 + tg) * 68
                                      + warpN2 * 32 + nt * 8 + gid;
                    b2[nt][0] = rna(pb[0]);
                    b2[nt][1] = rna(pb[4 * 68]);
                }
#pragma unroll
                for (int mt = 0; mt < 2; mt++)
#pragma unroll
                    for (int nt = 0; nt < 4; nt++)
                        mma_tf32(oacc[mt][nt], a2[mt], b2[nt]);
            }
        }
        __syncthreads();
    }

    // epilogue: oacc is already normalized (attn was normalized pre-MMA)
#pragma unroll
    for (int mt = 0; mt < 2; mt++) {
        int r = m0 + warpM2 * 32 + mt * 16 + gid;
#pragma unroll
        for (int nt = 0; nt < 4; nt++) {
            int cc = warpN2 * 32 + nt * 8 + tg * 2;
            *reinterpret_cast<float2*>(out + ((size_t)(bb * L_ + r)) * D_ + h * 64 + cc) =
                make_float2(oacc[mt][nt][0], oacc[mt][nt][1]);
            *reinterpret_cast<float2*>(out + ((size_t)(bb * L_ + r + 8)) * D_ + h * 64 + cc) =
                make_float2(oacc[mt][nt][2], oacc[mt][nt][3]);
        }
    }
}

// ---------------------------------------------------------------------------
extern "C" void kernel_launch(void* const* d_in, const int* in_sizes, int n_in,
                              void* d_out, int out_size)
{
    const float* queries = (const float*)d_in[0];
    const float* keys    = (const float*)d_in[1];
    const float* values  = (const float*)d_in[2];
    const float* Wq      = (const float*)d_in[3];
    const float* bq      = (const float*)d_in[4];
    const float* Wk      = (const float*)d_in[5];
    const float* bk      = (const float*)d_in[6];
    const float* Wv      = (const float*)d_in[7];
    const float* bv      = (const float*)d_in[8];

    float* out  = (float*)d_out;
    float* attn = out + (size_t)B_ * L_ * D_;   // tuple order: (out, attn)

    static bool attr_set = false;
    if (!attr_set) {
        cudaFuncSetAttribute(proj_mma,   cudaFuncAttributeMaxDynamicSharedMemorySize, PJ_SMEM);
        cudaFuncSetAttribute(fused_attn, cudaFuncAttributeMaxDynamicSharedMemorySize, F_SMEM);
        attr_set = true;
    }

    proj_mma<<<dim3((B_ * L_) / 128, D_ / 128, 3), 256, PJ_SMEM>>>(
        queries, keys, values, Wq, Wk, Wv, bq, bk, bv);
    fused_attn<<<dim3(L_ / 128, B_ * H_), 256, F_SMEM>>>(attn, out);
}

// round 9
// speedup vs baseline: 1.2610x; 1.2610x over previous
#include <cuda_runtime.h>
#include <cstdint>

#define B_ 4
#define L_ 2048
#define D_ 512
#define H_ 8
#define E_ 64

// Projected Q/K/V scratch, [B,H,L,E] (each (b,h) slice is contiguous [L,E]).
__device__ __align__(256) float g_q[B_ * H_ * L_ * E_];
__device__ __align__(256) float g_k[B_ * H_ * L_ * E_];
__device__ __align__(256) float g_v[B_ * H_ * L_ * E_];
// Per-row partial sums of exp(scores): [row_global][col_tile 0..15]
__device__ __align__(256) float g_psum[B_ * H_ * L_ * 16];

// ---------------------------------------------------------------------------
// helpers
// ---------------------------------------------------------------------------
__device__ __forceinline__ uint32_t smem_u32(const void* p) {
    uint32_t a;
    asm("{ .reg .u64 t; cvta.to.shared.u64 t, %1; cvt.u32.u64 %0, t; }"
        : "=r"(a) : "l"(p));
    return a;
}

// Round fp32 -> nearest tf32 (kills the truncation bias of the MMA datapath).
__device__ __forceinline__ uint32_t rna(float x) {
    uint32_t r;
    asm("cvt.rna.tf32.f32 %0, %1;" : "=r"(r) : "f"(x));
    return r;
}

// D = A(16x8,row) * B(8x8,col) + D, tf32 inputs
__device__ __forceinline__ void mma_tf32(float* d, const uint32_t* a, const uint32_t* b) {
    asm volatile(
        "mma.sync.aligned.m16n8k8.row.col.f32.tf32.tf32.f32 "
        "{%0,%1,%2,%3}, {%4,%5,%6,%7}, {%8,%9}, {%0,%1,%2,%3};"
        : "+f"(d[0]), "+f"(d[1]), "+f"(d[2]), "+f"(d[3])
        : "r"(a[0]), "r"(a[1]), "r"(a[2]), "r"(a[3]), "r"(b[0]), "r"(b[1]));
}

__device__ __forceinline__ void cp16(uint32_t dst, const void* src) {
    asm volatile("cp.async.cg.shared.global [%0], [%1], 16;"
                 :: "r"(dst), "l"(src) : "memory");
}
#define CP_COMMIT() asm volatile("cp.async.commit_group;" ::: "memory")
#define CP_WAIT(n)  asm volatile("cp.async.wait_group %0;" :: "n"(n) : "memory")

// streaming (evict-first) stores for the huge attn matrix
__device__ __forceinline__ void st_cs2(float* p, float x, float y) {
    asm volatile("st.global.cs.v2.f32 [%0], {%1, %2};" :: "l"(p), "f"(x), "f"(y) : "memory");
}
__device__ __forceinline__ void st_cs4(float* p, float4 v) {
    asm volatile("st.global.cs.v4.f32 [%0], {%1, %2, %3, %4};"
                 :: "l"(p), "f"(v.x), "f"(v.y), "f"(v.z), "f"(v.w) : "memory");
}

// ---------------------------------------------------------------------------
// Kernel 1: QKV projection (1x tf32, RN-rounded operands).
// CTA 128x128, 8 warps (2M x 4N), K=512 in BK=32 chunks, double buffer.
// grid (64, 4, 3), 256 thr.
// ---------------------------------------------------------------------------
static constexpr int PJ_XS = 128 * 36;
static constexpr int PJ_WS = 32 * 136;
static constexpr int PJ_SMEM = (2 * PJ_XS + 2 * PJ_WS) * 4;   // 71680 B

__global__ void __launch_bounds__(256, 2) proj_mma(
    const float* __restrict__ X0, const float* __restrict__ X1,
    const float* __restrict__ X2,
    const float* __restrict__ W0, const float* __restrict__ W1,
    const float* __restrict__ W2,
    const float* __restrict__ b0, const float* __restrict__ b1,
    const float* __restrict__ b2)
{
    extern __shared__ float smf[];
    float* Xs = smf;
    float* Ws = smf + 2 * PJ_XS;
    uint32_t sX = smem_u32(Xs), sW = smem_u32(Ws);

    int z = blockIdx.z;
    const float* X = (z == 0) ? X0 : (z == 1) ? X1 : X2;
    const float* W = (z == 0) ? W0 : (z == 1) ? W1 : W2;
    const float* bias = (z == 0) ? b0 : (z == 1) ? b1 : b2;
    float* dst = (z == 0) ? g_q : (z == 1) ? g_k : g_v;

    int t = threadIdx.x;
    int lane = t & 31, wid = t >> 5;
    int gid = lane >> 2, tg = lane & 3;
    int warpM = wid >> 2, warpN = wid & 3;
    int m0 = blockIdx.x * 128, n0 = blockIdx.y * 128;

    float acc[4][4][4] = {};

    auto stage = [&](int kt, int buf) {
        int k0 = kt * 32;
#pragma unroll
        for (int i = 0; i < 4; i++) {
            int idx = t + i * 256;
            int row = idx >> 3, cc = (idx & 7) * 4;
            cp16(sX + (buf * PJ_XS + row * 36 + cc) * 4,
                 X + (size_t)(m0 + row) * D_ + k0 + cc);
        }
#pragma unroll
        for (int i = 0; i < 4; i++) {
            int idx = t + i * 256;
            int row = idx >> 5, cc = (idx & 31) * 4;
            cp16(sW + (buf * PJ_WS + row * 136 + cc) * 4,
                 W + (size_t)(k0 + row) * D_ + n0 + cc);
        }
    };

    stage(0, 0); CP_COMMIT();
    const int NIT = D_ / 32;                 // 16
    for (int kt = 0; kt < NIT; kt++) {
        int p = kt & 1;
        if (kt + 1 < NIT) { stage(kt + 1, p ^ 1); CP_COMMIT(); CP_WAIT(1); }
        else              { CP_WAIT(0); }
        __syncthreads();

        const float* Ab = Xs + p * PJ_XS;
        const float* Bb = Ws + p * PJ_WS;
#pragma unroll
        for (int ks = 0; ks < 4; ks++) {
            int k0 = ks * 8;
            uint32_t a[4][4], b[4][2];
#pragma unroll
            for (int mt = 0; mt < 4; mt++) {
                const float* pa = Ab + (warpM * 64 + mt * 16 + gid) * 36 + k0 + tg;
                a[mt][0] = rna(pa[0]);
                a[mt][1] = rna(pa[8 * 36]);
                a[mt][2] = rna(pa[4]);
                a[mt][3] = rna(pa[8 * 36 + 4]);
            }
#pragma unroll
            for (int nt = 0; nt < 4; nt++) {
                const float* pb = Bb + (k0 + tg) * 136 + warpN * 32 + nt * 8 + gid;
                b[nt][0] = rna(pb[0]);
                b[nt][1] = rna(pb[4 * 136]);
            }
#pragma unroll
            for (int mt = 0; mt < 4; mt++)
#pragma unroll
                for (int nt = 0; nt < 4; nt++)
                    mma_tf32(acc[mt][nt], a[mt], b[nt]);
        }
        __syncthreads();
    }

#pragma unroll
    for (int mt = 0; mt < 4; mt++) {
        int m = m0 + warpM * 64 + mt * 16 + gid;
        int bb = m >> 11;
        int l  = m & (L_ - 1);
#pragma unroll
        for (int nt = 0; nt < 4; nt++) {
            int n = n0 + warpN * 32 + nt * 8 + tg * 2;
            int h = n >> 6, e = n & 63;
            float2 bi = *reinterpret_cast<const float2*>(bias + n);
            *reinterpret_cast<float2*>(dst + (((size_t)(bb * H_ + h)) * L_ + l) * E_ + e) =
                make_float2(acc[mt][nt][0] + bi.x, acc[mt][nt][1] + bi.y);
            *reinterpret_cast<float2*>(dst + (((size_t)(bb * H_ + h)) * L_ + l + 8) * E_ + e) =
                make_float2(acc[mt][nt][2] + bi.x, acc[mt][nt][3] + bi.y);
        }
    }
}

// ---------------------------------------------------------------------------
// Kernel 2: scores + exp (1x tf32, RN-rounded).  Writes p = exp(scale*QK^T)
// (unnormalized) into attn via streaming stores, partial row sums into g_psum.
// CTA 128x128, full K=64 resident.  grid (16,16,32), 256 threads, 2 CTAs/SM.
// ---------------------------------------------------------------------------
static constexpr int S_SMEM = (2 * 128 * 68 + 4 * 128) * 4;   // 71680 B

__global__ void __launch_bounds__(256, 2) scores_mma(float* __restrict__ attn)
{
    extern __shared__ float smf[];
    float* Qs = smf;
    float* Ks = smf + 128 * 68;
    float* red = smf + 2 * 128 * 68;         // [4][128]

    int t = threadIdx.x;
    int lane = t & 31, wid = t >> 5;
    int gid = lane >> 2, tg = lane & 3;
    int warpM = wid >> 2, warpN = wid & 3;
    int m0 = blockIdx.x * 128, n0 = blockIdx.y * 128, bh = blockIdx.z;

    const float* Q = g_q + (size_t)bh * L_ * E_;
    const float* K = g_k + (size_t)bh * L_ * E_;
    float* S = attn + (size_t)bh * L_ * L_;

#pragma unroll
    for (int i = 0; i < 8; i++) {
        int idx = t + i * 256;
        int row = idx >> 4, cc = (idx & 15) * 4;
        *reinterpret_cast<float4*>(Qs + row * 68 + cc) =
            *reinterpret_cast<const float4*>(Q + (size_t)(m0 + row) * E_ + cc);
        *reinterpret_cast<float4*>(Ks + row * 68 + cc) =
            *reinterpret_cast<const float4*>(K + (size_t)(n0 + row) * E_ + cc);
    }
    __syncthreads();

    float acc[4][4][4] = {};
#pragma unroll
    for (int ks = 0; ks < 8; ks++) {
        int k0 = ks * 8;
        uint32_t a[4][4], b[4][2];
#pragma unroll
        for (int mt = 0; mt < 4; mt++) {
            const float* pa = Qs + (warpM * 64 + mt * 16 + gid) * 68 + k0 + tg;
            a[mt][0] = rna(pa[0]);
            a[mt][1] = rna(pa[8 * 68]);
            a[mt][2] = rna(pa[4]);
            a[mt][3] = rna(pa[8 * 68 + 4]);
        }
#pragma unroll
        for (int nt = 0; nt < 4; nt++) {
            const float* pb = Ks + (warpN * 32 + nt * 8 + gid) * 68 + k0 + tg;
            b[nt][0] = rna(pb[0]);
            b[nt][1] = rna(pb[4]);
        }
#pragma unroll
        for (int mt = 0; mt < 4; mt++)
#pragma unroll
            for (int nt = 0; nt < 4; nt++)
                mma_tf32(acc[mt][nt], a[mt], b[nt]);
    }

    const float scale = 0.125f;
    float rowpart[4][2] = {};                 // [mt][half]
#pragma unroll
    for (int mt = 0; mt < 4; mt++) {
        int r = m0 + warpM * 64 + mt * 16 + gid;
#pragma unroll
        for (int nt = 0; nt < 4; nt++) {
            int cc = n0 + warpN * 32 + nt * 8 + tg * 2;
            float p0 = __expf(acc[mt][nt][0] * scale);
            float p1 = __expf(acc[mt][nt][1] * scale);
            float p2 = __expf(acc[mt][nt][2] * scale);
            float p3 = __expf(acc[mt][nt][3] * scale);
            st_cs2(S + (size_t)r * L_ + cc, p0, p1);
            st_cs2(S + (size_t)(r + 8) * L_ + cc, p2, p3);
            rowpart[mt][0] += p0 + p1;
            rowpart[mt][1] += p2 + p3;
        }
    }

    // reduce partial row sums over tg lanes, then over warpN via SMEM
#pragma unroll
    for (int mt = 0; mt < 4; mt++) {
#pragma unroll
        for (int half = 0; half < 2; half++) {
            float v = rowpart[mt][half];
            v += __shfl_xor_sync(0xffffffffu, v, 1);
            v += __shfl_xor_sync(0xffffffffu, v, 2);
            if (tg == 0)
                red[warpN * 128 + warpM * 64 + mt * 16 + gid + half * 8] = v;
        }
    }
    __syncthreads();
    if (t < 128) {
        float s = red[t] + red[128 + t] + red[256 + t] + red[384 + t];
        g_psum[((size_t)bh * L_ + m0 + t) * 16 + blockIdx.y] = s;
    }
}

// ---------------------------------------------------------------------------
// Kernel 3: AV (1x tf32, RN-rounded) fused with softmax-normalize.
// Reads unnormalized exp from attn, writes normalized attn back in place
// (streaming stores), computes out = (attn_norm @ V).
// CTA 128x64, 3-stage cp.async.  grid (16,1,32), 256 threads, 2 CTAs/SM.
// ---------------------------------------------------------------------------
static constexpr int AV_AS = 128 * 36;
static constexpr int AV_BS = 32 * 72;
static constexpr int AV_SMEM = (3 * AV_AS + 3 * AV_BS + 128) * 4;   // 83456 B

__global__ void __launch_bounds__(256, 2) av_mma(float* __restrict__ attn,
                                                 float* __restrict__ out)
{
    extern __shared__ float smf[];
    float* As = smf;
    float* Bs = smf + 3 * AV_AS;
    float* rowinv = smf + 3 * AV_AS + 3 * AV_BS;
    uint32_t sA = smem_u32(As), sB = smem_u32(Bs);

    int t = threadIdx.x;
    int lane = t & 31, wid = t >> 5;
    int gid = lane >> 2, tg = lane & 3;
    int warpM = wid >> 1, warpN = wid & 1;
    int m0 = blockIdx.x * 128, bh = blockIdx.z;
    int bb = bh >> 3, h = bh & 7;

    float* A = attn + (size_t)bh * L_ * L_;
    const float* V = g_v + (size_t)bh * L_ * E_;

    float acc[2][4][4] = {};

    auto stage = [&](int kt, int buf) {
        int k0 = kt * 32;
#pragma unroll
        for (int i = 0; i < 4; i++) {
            int idx = t + i * 256;            // attn 128x32
            int row = idx >> 3, cc = (idx & 7) * 4;
            cp16(sA + (buf * AV_AS + row * 36 + cc) * 4,
                 A + (size_t)(m0 + row) * L_ + k0 + cc);
        }
#pragma unroll
        for (int i = 0; i < 2; i++) {
            int idx = t + i * 256;            // V 32x64
            int row = idx >> 4, cc = (idx & 15) * 4;
            cp16(sB + (buf * AV_BS + row * 72 + cc) * 4,
                 V + (size_t)(k0 + row) * E_ + cc);
        }
    };

    const int NIT = L_ / 32;                  // 64
    stage(0, 0); CP_COMMIT();
    stage(1, 1); CP_COMMIT();

    // row sums -> 1/sum
    if (t < 128) {
        const float* pp = g_psum + ((size_t)bh * L_ + m0 + t) * 16;
        float s = 0.f;
#pragma unroll
        for (int j = 0; j < 16; j++) s += pp[j];
        rowinv[t] = 1.0f / s;
    }

    for (int kt = 0; kt < NIT; kt++) {
        __syncthreads();
        if (kt + 2 < NIT) { stage(kt + 2, (kt + 2) % 3); CP_COMMIT(); CP_WAIT(2); }
        else if (kt + 1 < NIT) { CP_WAIT(1); }
        else { CP_WAIT(0); }
        __syncthreads();

        int p = kt % 3;
        const float* Ab = As + p * AV_AS;
        const float* Bb = Bs + p * AV_BS;

        // normalized write-back of this attn tile (SMEM stays unnormalized;
        // the out epilogue applies 1/rowsum to the accumulators)
        {
            int k0 = kt * 32;
#pragma unroll
            for (int i = 0; i < 4; i++) {
                int idx = t + i * 256;
                int row = idx >> 3, cc = (idx & 7) * 4;
                float4 v = *reinterpret_cast<const float4*>(Ab + row * 36 + cc);
                float s = rowinv[row];
                v.x *= s; v.y *= s; v.z *= s; v.w *= s;
                st_cs4(A + (size_t)(m0 + row) * L_ + k0 + cc, v);
            }
        }

#pragma unroll
        for (int ks = 0; ks < 4; ks++) {
            int k0 = ks * 8;
            uint32_t a[2][4], b[4][2];
#pragma unroll
            for (int mt = 0; mt < 2; mt++) {
                const float* pa = Ab + (warpM * 32 + mt * 16 + gid) * 36 + k0 + tg;
                a[mt][0] = rna(pa[0]);
                a[mt][1] = rna(pa[8 * 36]);
                a[mt][2] = rna(pa[4]);
                a[mt][3] = rna(pa[8 * 36 + 4]);
            }
#pragma unroll
            for (int nt = 0; nt < 4; nt++) {
                const float* pb = Bb + (k0 + tg) * 72 + warpN * 32 + nt * 8 + gid;
                b[nt][0] = rna(pb[0]);
                b[nt][1] = rna(pb[4 * 72]);
            }
#pragma unroll
            for (int mt = 0; mt < 2; mt++)
#pragma unroll
                for (int nt = 0; nt < 4; nt++)
                    mma_tf32(acc[mt][nt], a[mt], b[nt]);
        }
    }

#pragma unroll
    for (int mt = 0; mt < 2; mt++) {
        int rloc = warpM * 32 + mt * 16 + gid;
        int r = m0 + rloc;
        float s0 = rowinv[rloc], s1 = rowinv[rloc + 8];
#pragma unroll
        for (int nt = 0; nt < 4; nt++) {
            int cc = warpN * 32 + nt * 8 + tg * 2;
            *reinterpret_cast<float2*>(out + ((size_t)(bb * L_ + r)) * D_ + h * 64 + cc) =
                make_float2(acc[mt][nt][0] * s0, acc[mt][nt][1] * s0);
            *reinterpret_cast<float2*>(out + ((size_t)(bb * L_ + r + 8)) * D_ + h * 64 + cc) =
                make_float2(acc[mt][nt][2] * s1, acc[mt][nt][3] * s1);
        }
    }
}

// ---------------------------------------------------------------------------
extern "C" void kernel_launch(void* const* d_in, const int* in_sizes, int n_in,
                              void* d_out, int out_size)
{
    const float* queries = (const float*)d_in[0];
    const float* keys    = (const float*)d_in[1];
    const float* values  = (const float*)d_in[2];
    const float* Wq      = (const float*)d_in[3];
    const float* bq      = (const float*)d_in[4];
    const float* Wk      = (const float*)d_in[5];
    const float* bk      = (const float*)d_in[6];
    const float* Wv      = (const float*)d_in[7];
    const float* bv      = (const float*)d_in[8];

    float* out  = (float*)d_out;
    float* attn = out + (size_t)B_ * L_ * D_;   // tuple order: (out, attn)

    static bool attr_set = false;
    if (!attr_set) {
        cudaFuncSetAttribute(proj_mma,   cudaFuncAttributeMaxDynamicSharedMemorySize, PJ_SMEM);
        cudaFuncSetAttribute(scores_mma, cudaFuncAttributeMaxDynamicSharedMemorySize, S_SMEM);
        cudaFuncSetAttribute(av_mma,     cudaFuncAttributeMaxDynamicSharedMemorySize, AV_SMEM);
        attr_set = true;
    }

    proj_mma<<<dim3((B_ * L_) / 128, D_ / 128, 3), 256, PJ_SMEM>>>(
        queries, keys, values, Wq, Wk, Wv, bq, bk, bv);
    scores_mma<<<dim3(L_ / 128, L_ / 128, B_ * H_), 256, S_SMEM>>>(attn);
    av_mma<<<dim3(L_ / 128, 1, B_ * H_), 256, AV_SMEM>>>(attn, out);
}